// round 13
// baseline (speedup 1.0000x reference)
#include <cuda_runtime.h>
#include <cuda_bf16.h>

#define BATCH   2048
#define N0      49
#define CH      768
#define MID     48
#define K1      36
#define K2      24
#define THREADS 128
#define WARPS   4

// Preprocessed weights (device globals). R2/R10 layouts.
//   g_w1t[r][j*CH + c] = bf16( se{r}_w1[c, j] )
//   g_w2 [r][j*CH + c] = bf16( se{r}_w2[j, c] )
//   g_clswt[o*CH + c]  = cls_w[c, o]  fp32
__device__ __nv_bfloat16 g_w1t[2][MID * CH];
__device__ __nv_bfloat16 g_w2 [2][MID * CH];
__device__ float         g_clswt[5 * CH];

__global__ void convert_weights_kernel(const float* __restrict__ w1a,
                                       const float* __restrict__ w2a,
                                       const float* __restrict__ w1b,
                                       const float* __restrict__ w2b,
                                       const float* __restrict__ clsw) {
    int i = blockIdx.x * blockDim.x + threadIdx.x;
    if (i < MID * CH) {
        int j = i / CH;
        int c = i - j * CH;
        g_w1t[0][i] = __float2bfloat16(w1a[c * MID + j]);
        g_w1t[1][i] = __float2bfloat16(w1b[c * MID + j]);
        g_w2 [0][i] = __float2bfloat16(w2a[i]);
        g_w2 [1][i] = __float2bfloat16(w2b[i]);
    }
    if (i < 5 * CH) {
        int o = i / CH;
        int c = i - o * CH;
        g_clswt[i] = clsw[c * 5 + o];
    }
}

// Shared memory (floats): sbuf[CH], csum[CH], gat[CH], hbuf[MID],
// ts[64], list[40] int, uns[16] int, uns2[16] int, red[80]
#define SM_FLOATS (CH + CH + CH + MID + 64 + 40 + 16 + 16 + 80)
#define SM_BYTES  (SM_FLOATS * 4)

__global__ __launch_bounds__(THREADS, 8)
void coatgft_kernel(const float* __restrict__ x,
                    const float* __restrict__ b1a, const float* __restrict__ b2a,
                    const float* __restrict__ b1b, const float* __restrict__ b2b,
                    const float* __restrict__ ln_g, const float* __restrict__ ln_b,
                    const float* __restrict__ cls_b,
                    float* __restrict__ out) {
    extern __shared__ float sm[];
    float* sbuf = sm;                    // [CH]
    float* csum = sbuf + CH;             // [CH]
    float* gat  = csum + CH;             // [CH]
    float* hbuf = gat + CH;              // [MID]
    float* ts   = hbuf + MID;            // [64]
    int*   list = (int*)(ts + 64);       // [40]
    int*   uns  = list + 40;             // [16]
    int*   uns2 = uns + 16;              // [16]
    float* red  = (float*)(uns2 + 16);   // [80]

    const int tid  = threadIdx.x;
    const int lane = tid & 31;
    const int warp = tid >> 5;
    const int b    = blockIdx.x;
    const float* __restrict__ xb = x + (size_t)b * N0 * CH;

    // ---- 1. colmean + colsum over 49 rows: 6 channels per thread (L2-only) --
    {
        float a0 = 0.f, a1 = 0.f, a2 = 0.f, a3 = 0.f, a4 = 0.f, a5 = 0.f;
        #pragma unroll 7
        for (int r = 0; r < N0; r++) {
            const float* row = xb + (size_t)r * CH;
            a0 += __ldcg(row + tid);
            a1 += __ldcg(row + tid + 128);
            a2 += __ldcg(row + tid + 256);
            a3 += __ldcg(row + tid + 384);
            a4 += __ldcg(row + tid + 512);
            a5 += __ldcg(row + tid + 640);
        }
        csum[tid]       = a0;  sbuf[tid]       = a0 * (1.0f / (float)N0);
        csum[tid + 128] = a1;  sbuf[tid + 128] = a1 * (1.0f / (float)N0);
        csum[tid + 256] = a2;  sbuf[tid + 256] = a2 * (1.0f / (float)N0);
        csum[tid + 384] = a3;  sbuf[tid + 384] = a3 * (1.0f / (float)N0);
        csum[tid + 512] = a4;  sbuf[tid + 512] = a4 * (1.0f / (float)N0);
        csum[tid + 640] = a5;  sbuf[tid + 640] = a5 * (1.0f / (float)N0);
    }
    __syncthreads();

    // ======================= ROUND 1 (49 -> 36) =============================
    {   // h = gelu(s @ W1 + b1): 12 outputs per warp
        const __nv_bfloat162* W1t = (const __nv_bfloat162*)g_w1t[0];
        #pragma unroll
        for (int jj = 0; jj < 12; jj++) {
            int j = warp + jj * WARPS;
            const __nv_bfloat162* wr = W1t + j * (CH / 2);
            float acc = 0.f;
            #pragma unroll
            for (int k = 0; k < CH / 64; k++) {
                int p = lane + 32 * k;
                __nv_bfloat162 w = wr[p];
                acc += sbuf[2 * p] * __low2float(w) + sbuf[2 * p + 1] * __high2float(w);
            }
            #pragma unroll
            for (int o = 16; o; o >>= 1) acc += __shfl_xor_sync(0xffffffffu, acc, o);
            if (lane == 0) {
                float z = acc + b1a[j];
                hbuf[j] = 0.5f * z * (1.0f + erff(z * 0.70710678118654752f));
            }
        }
    }
    __syncthreads();

    // gates1: 6 channels per thread (W2 coalesced)
    {
        const __nv_bfloat16* W2 = g_w2[0];
        float a0 = b2a[tid],       a1 = b2a[tid + 128], a2 = b2a[tid + 256];
        float a3 = b2a[tid + 384], a4 = b2a[tid + 512], a5 = b2a[tid + 640];
        #pragma unroll
        for (int j = 0; j < MID; j++) {
            float h = hbuf[j];
            const __nv_bfloat16* wj = W2 + j * CH;
            a0 += h * __bfloat162float(wj[tid]);
            a1 += h * __bfloat162float(wj[tid + 128]);
            a2 += h * __bfloat162float(wj[tid + 256]);
            a3 += h * __bfloat162float(wj[tid + 384]);
            a4 += h * __bfloat162float(wj[tid + 512]);
            a5 += h * __bfloat162float(wj[tid + 640]);
        }
        gat[tid]       = 1.0f / (1.0f + expf(-a0));
        gat[tid + 128] = 1.0f / (1.0f + expf(-a1));
        gat[tid + 256] = 1.0f / (1.0f + expf(-a2));
        gat[tid + 384] = 1.0f / (1.0f + expf(-a3));
        gat[tid + 512] = 1.0f / (1.0f + expf(-a4));
        gat[tid + 640] = 1.0f / (1.0f + expf(-a5));
    }
    __syncthreads();

    // ts1[r] = sum_c (x*g)^2: warp per row, x from L2 (float4), g from smem
    {
        const float4* g4p = (const float4*)gat;
        #pragma unroll
        for (int ii = 0; ii < 13; ii++) {
            int r = warp + ii * WARPS;
            if (r < N0) {
                const float4* row = (const float4*)(xb + (size_t)r * CH);
                float acc = 0.f;
                #pragma unroll
                for (int k = 0; k < 6; k++) {
                    float4 a = __ldcg(row + lane + 32 * k);
                    float4 g = g4p[lane + 32 * k];
                    float v;
                    v = a.x * g.x; acc += v * v;
                    v = a.y * g.y; acc += v * v;
                    v = a.z * g.z; acc += v * v;
                    v = a.w * g.w; acc += v * v;
                }
                #pragma unroll
                for (int o = 16; o; o >>= 1) acc += __shfl_xor_sync(0xffffffffu, acc, o);
                if (lane == 0) ts[r] = acc;
            }
        }
    }
    __syncthreads();

    // rank-select top-36 (== jax top_k order); 13 unselected to uns
    if (tid < N0) {
        float mine = ts[tid];
        int rank = 0;
        #pragma unroll
        for (int j = 0; j < N0; j++) {
            float tj = ts[j];
            rank += (tj > mine) || (tj == mine && j < tid);
        }
        if (rank < K1) list[rank] = tid;
        else           uns[rank - K1] = tid;
    }
    __syncthreads();

    // ======================= ROUND 2 (36 -> 24) =============================
    // csum36 = csum49 - 13 unselected rows; s2 = gat*csum36/36
    {
        float c0 = csum[tid],       c1 = csum[tid + 128], c2 = csum[tid + 256];
        float c3 = csum[tid + 384], c4 = csum[tid + 512], c5 = csum[tid + 640];
        #pragma unroll
        for (int i = 0; i < N0 - K1; i++) {
            const float* row = xb + (size_t)uns[i] * CH;
            c0 -= __ldcg(row + tid);
            c1 -= __ldcg(row + tid + 128);
            c2 -= __ldcg(row + tid + 256);
            c3 -= __ldcg(row + tid + 384);
            c4 -= __ldcg(row + tid + 512);
            c5 -= __ldcg(row + tid + 640);
        }
        csum[tid] = c0;       sbuf[tid]       = c0 * gat[tid]       * (1.0f / (float)K1);
        csum[tid + 128] = c1; sbuf[tid + 128] = c1 * gat[tid + 128] * (1.0f / (float)K1);
        csum[tid + 256] = c2; sbuf[tid + 256] = c2 * gat[tid + 256] * (1.0f / (float)K1);
        csum[tid + 384] = c3; sbuf[tid + 384] = c3 * gat[tid + 384] * (1.0f / (float)K1);
        csum[tid + 512] = c4; sbuf[tid + 512] = c4 * gat[tid + 512] * (1.0f / (float)K1);
        csum[tid + 640] = c5; sbuf[tid + 640] = c5 * gat[tid + 640] * (1.0f / (float)K1);
    }
    __syncthreads();

    {
        const __nv_bfloat162* W1t = (const __nv_bfloat162*)g_w1t[1];
        #pragma unroll
        for (int jj = 0; jj < 12; jj++) {
            int j = warp + jj * WARPS;
            const __nv_bfloat162* wr = W1t + j * (CH / 2);
            float acc = 0.f;
            #pragma unroll
            for (int k = 0; k < CH / 64; k++) {
                int p = lane + 32 * k;
                __nv_bfloat162 w = wr[p];
                acc += sbuf[2 * p] * __low2float(w) + sbuf[2 * p + 1] * __high2float(w);
            }
            #pragma unroll
            for (int o = 16; o; o >>= 1) acc += __shfl_xor_sync(0xffffffffu, acc, o);
            if (lane == 0) {
                float z = acc + b1b[j];
                hbuf[j] = 0.5f * z * (1.0f + erff(z * 0.70710678118654752f));
            }
        }
    }
    __syncthreads();

    // gat *= gates2
    {
        const __nv_bfloat16* W2 = g_w2[1];
        float a0 = b2b[tid],       a1 = b2b[tid + 128], a2 = b2b[tid + 256];
        float a3 = b2b[tid + 384], a4 = b2b[tid + 512], a5 = b2b[tid + 640];
        #pragma unroll
        for (int j = 0; j < MID; j++) {
            float h = hbuf[j];
            const __nv_bfloat16* wj = W2 + j * CH;
            a0 += h * __bfloat162float(wj[tid]);
            a1 += h * __bfloat162float(wj[tid + 128]);
            a2 += h * __bfloat162float(wj[tid + 256]);
            a3 += h * __bfloat162float(wj[tid + 384]);
            a4 += h * __bfloat162float(wj[tid + 512]);
            a5 += h * __bfloat162float(wj[tid + 640]);
        }
        gat[tid]       *= 1.0f / (1.0f + expf(-a0));
        gat[tid + 128] *= 1.0f / (1.0f + expf(-a1));
        gat[tid + 256] *= 1.0f / (1.0f + expf(-a2));
        gat[tid + 384] *= 1.0f / (1.0f + expf(-a3));
        gat[tid + 512] *= 1.0f / (1.0f + expf(-a4));
        gat[tid + 640] *= 1.0f / (1.0f + expf(-a5));
    }
    __syncthreads();

    // ts2 over 36 selected rows (cumulative gate)
    {
        const float4* g4p = (const float4*)gat;
        #pragma unroll
        for (int ii = 0; ii < 9; ii++) {
            int i = warp + ii * WARPS;
            if (i < K1) {
                const float4* row = (const float4*)(xb + (size_t)list[i] * CH);
                float acc = 0.f;
                #pragma unroll
                for (int k = 0; k < 6; k++) {
                    float4 a = __ldcg(row + lane + 32 * k);
                    float4 g = g4p[lane + 32 * k];
                    float v;
                    v = a.x * g.x; acc += v * v;
                    v = a.y * g.y; acc += v * v;
                    v = a.z * g.z; acc += v * v;
                    v = a.w * g.w; acc += v * v;
                }
                #pragma unroll
                for (int o = 16; o; o >>= 1) acc += __shfl_xor_sync(0xffffffffu, acc, o);
                if (lane == 0) ts[i] = acc;
            }
        }
    }
    __syncthreads();

    // top-24 of 36: record the 12 removed rows
    if (tid < K1) {
        float mine = ts[tid];
        int rank = 0;
        int row = list[tid];
        #pragma unroll
        for (int j = 0; j < K1; j++) {
            float tj = ts[j];
            rank += (tj > mine) || (tj == mine && j < tid);
        }
        if (rank >= K2) uns2[rank - K2] = row;
    }
    __syncthreads();

    // pooled = gat * (csum36 - 12 removed rows) / 24
    {
        float c0 = csum[tid],       c1 = csum[tid + 128], c2 = csum[tid + 256];
        float c3 = csum[tid + 384], c4 = csum[tid + 512], c5 = csum[tid + 640];
        #pragma unroll
        for (int i = 0; i < K1 - K2; i++) {
            const float* row = xb + (size_t)uns2[i] * CH;
            c0 -= __ldcg(row + tid);
            c1 -= __ldcg(row + tid + 128);
            c2 -= __ldcg(row + tid + 256);
            c3 -= __ldcg(row + tid + 384);
            c4 -= __ldcg(row + tid + 512);
            c5 -= __ldcg(row + tid + 640);
        }
        sbuf[tid]       = c0 * gat[tid]       * (1.0f / (float)K2);
        sbuf[tid + 128] = c1 * gat[tid + 128] * (1.0f / (float)K2);
        sbuf[tid + 256] = c2 * gat[tid + 256] * (1.0f / (float)K2);
        sbuf[tid + 384] = c3 * gat[tid + 384] * (1.0f / (float)K2);
        sbuf[tid + 512] = c4 * gat[tid + 512] * (1.0f / (float)K2);
        sbuf[tid + 640] = c5 * gat[tid + 640] * (1.0f / (float)K2);
    }
    __syncthreads();

    // ---- LayerNorm stats ----
    {
        float v0 = sbuf[tid],       v1 = sbuf[tid + 128], v2 = sbuf[tid + 256];
        float v3 = sbuf[tid + 384], v4 = sbuf[tid + 512], v5 = sbuf[tid + 640];
        float p1 = v0 + v1 + v2 + v3 + v4 + v5;
        float p2 = v0*v0 + v1*v1 + v2*v2 + v3*v3 + v4*v4 + v5*v5;
        #pragma unroll
        for (int o = 16; o; o >>= 1) {
            p1 += __shfl_xor_sync(0xffffffffu, p1, o);
            p2 += __shfl_xor_sync(0xffffffffu, p2, o);
        }
        if (lane == 0) { red[warp] = p1; red[8 + warp] = p2; }
        __syncthreads();
        if (warp == 0) {
            float m  = (lane < WARPS) ? red[lane]     : 0.f;
            float m2 = (lane < WARPS) ? red[8 + lane] : 0.f;
            #pragma unroll
            for (int o = 2; o; o >>= 1) {
                m  += __shfl_xor_sync(0xffffffffu, m,  o);
                m2 += __shfl_xor_sync(0xffffffffu, m2, o);
            }
            if (lane == 0) {
                m  *= (1.0f / CH);
                m2 *= (1.0f / CH);
                red[16] = m;
                red[17] = rsqrtf(m2 - m * m + 1e-5f);
            }
        }
        __syncthreads();
        float mu = red[16], inv = red[17];
        gat[tid]       = (v0 - mu) * inv * ln_g[tid]       + ln_b[tid];
        gat[tid + 128] = (v1 - mu) * inv * ln_g[tid + 128] + ln_b[tid + 128];
        gat[tid + 256] = (v2 - mu) * inv * ln_g[tid + 256] + ln_b[tid + 256];
        gat[tid + 384] = (v3 - mu) * inv * ln_g[tid + 384] + ln_b[tid + 384];
        gat[tid + 512] = (v4 - mu) * inv * ln_g[tid + 512] + ln_b[tid + 512];
        gat[tid + 640] = (v5 - mu) * inv * ln_g[tid + 640] + ln_b[tid + 640];
    }
    __syncthreads();

    // ---- classifier: 5 outputs over 4 warps (warp 0 takes {0,4}) ----
    for (int o5 = warp; o5 < 5; o5 += WARPS) {
        const float* wr = g_clswt + o5 * CH;
        float acc = 0.f;
        #pragma unroll
        for (int k = 0; k < CH / 32; k++)
            acc += gat[lane + 32 * k] * wr[lane + 32 * k];
        #pragma unroll
        for (int o = 16; o; o >>= 1) acc += __shfl_xor_sync(0xffffffffu, acc, o);
        if (lane == 0) out[b * 5 + o5] = acc + cls_b[o5];
    }
}

extern "C" void kernel_launch(void* const* d_in, const int* in_sizes, int n_in,
                              void* d_out, int out_size) {
    const float* x    = (const float*)d_in[0];
    const float* w1a  = (const float*)d_in[1];
    const float* b1a  = (const float*)d_in[2];
    const float* w2a  = (const float*)d_in[3];
    const float* b2a  = (const float*)d_in[4];
    const float* w1b  = (const float*)d_in[5];
    const float* b1b  = (const float*)d_in[6];
    const float* w2b  = (const float*)d_in[7];
    const float* b2b  = (const float*)d_in[8];
    const float* lng  = (const float*)d_in[9];
    const float* lnb  = (const float*)d_in[10];
    const float* clsw = (const float*)d_in[11];
    const float* clsb = (const float*)d_in[12];
    float* out = (float*)d_out;

    cudaFuncSetAttribute(coatgft_kernel,
                         cudaFuncAttributeMaxDynamicSharedMemorySize, SM_BYTES);

    convert_weights_kernel<<<(MID * CH + 255) / 256, 256>>>(w1a, w2a, w1b, w2b, clsw);
    coatgft_kernel<<<BATCH, THREADS, SM_BYTES>>>(x, b1a, b2a, b1b, b2b,
                                                 lng, lnb, clsb, out);
}

// round 14
// speedup vs baseline: 1.3285x; 1.3285x over previous
#include <cuda_runtime.h>
#include <cuda_bf16.h>

#define BATCH   2048
#define N0      49
#define CH      768
#define MID     48
#define K1      36
#define K2      24
#define THREADS 256
#define WARPS   8

// Preprocessed weights (device globals).
//   g_w1t[r][j*CH + c] = bf16( se{r}_w1[c, j] )        (row j = 768 contiguous bf16)
//   g_w2p[r][((j/4)*CH + c)*4 + (j%4)] = bf16(w2[j,c])  (4 j's packed per 8B, coalesced in c)
//   g_clswt[o*CH + c]  = cls_w[c, o]  fp32
__device__ __nv_bfloat16 g_w1t[2][MID * CH];
__device__ __nv_bfloat16 g_w2p[2][MID * CH];
__device__ float         g_clswt[5 * CH];

__global__ void convert_weights_kernel(const float* __restrict__ w1a,
                                       const float* __restrict__ w2a,
                                       const float* __restrict__ w1b,
                                       const float* __restrict__ w2b,
                                       const float* __restrict__ clsw) {
    int i = blockIdx.x * blockDim.x + threadIdx.x;
    if (i < MID * CH) {
        int j = i / CH;
        int c = i - j * CH;
        g_w1t[0][i] = __float2bfloat16(w1a[c * MID + j]);
        g_w1t[1][i] = __float2bfloat16(w1b[c * MID + j]);
        int pidx = ((j >> 2) * CH + c) * 4 + (j & 3);
        g_w2p[0][pidx] = __float2bfloat16(w2a[i]);
        g_w2p[1][pidx] = __float2bfloat16(w2b[i]);
    }
    if (i < 5 * CH) {
        int o = i / CH;
        int c = i - o * CH;
        g_clswt[i] = clsw[c * 5 + o];
    }
}

// Shared memory (floats): sbuf[CH], csum[CH], gat[CH], hbuf[MID],
// ts[64], list[40] int, uns[16] int, uns2[16] int, red[80]
#define SM_FLOATS (CH + CH + CH + MID + 64 + 40 + 16 + 16 + 80)
#define SM_BYTES  (SM_FLOATS * 4)

// W1 GEMV partial: row j of W1t read as uint2 (4 bf16), sbuf as float4
__device__ __forceinline__ float w1_dot(const __nv_bfloat16* __restrict__ w1row,
                                        const float4* __restrict__ s4, int lane) {
    const uint2* wr = (const uint2*)w1row;
    float acc = 0.f;
    #pragma unroll
    for (int k = 0; k < 6; k++) {
        int p = lane + 32 * k;
        uint2 u = wr[p];
        __nv_bfloat162 h0 = *reinterpret_cast<__nv_bfloat162*>(&u.x);
        __nv_bfloat162 h1 = *reinterpret_cast<__nv_bfloat162*>(&u.y);
        float4 s = s4[p];
        acc += s.x * __low2float(h0) + s.y * __high2float(h0)
             + s.z * __low2float(h1) + s.w * __high2float(h1);
    }
    return acc;
}

// gates GEMV for one channel c: packed W2, 12 x LDG.64
__device__ __forceinline__ float w2_dot(const uint2* __restrict__ W2p,
                                        const float* __restrict__ hbuf, int c) {
    float acc = 0.f;
    #pragma unroll
    for (int j4 = 0; j4 < MID / 4; j4++) {
        uint2 u = W2p[j4 * CH + c];
        __nv_bfloat162 p0 = *reinterpret_cast<__nv_bfloat162*>(&u.x);
        __nv_bfloat162 p1 = *reinterpret_cast<__nv_bfloat162*>(&u.y);
        acc += hbuf[4 * j4]     * __low2float(p0)
             + hbuf[4 * j4 + 1] * __high2float(p0)
             + hbuf[4 * j4 + 2] * __low2float(p1)
             + hbuf[4 * j4 + 3] * __high2float(p1);
    }
    return acc;
}

__global__ __launch_bounds__(THREADS, 4)
void coatgft_kernel(const float* __restrict__ x,
                    const float* __restrict__ b1a, const float* __restrict__ b2a,
                    const float* __restrict__ b1b, const float* __restrict__ b2b,
                    const float* __restrict__ ln_g, const float* __restrict__ ln_b,
                    const float* __restrict__ cls_b,
                    float* __restrict__ out) {
    extern __shared__ float sm[];
    float* sbuf = sm;                    // [CH]
    float* csum = sbuf + CH;             // [CH]
    float* gat  = csum + CH;             // [CH]
    float* hbuf = gat + CH;              // [MID]
    float* ts   = hbuf + MID;            // [64]
    int*   list = (int*)(ts + 64);       // [40]
    int*   uns  = list + 40;             // [16]
    int*   uns2 = uns + 16;              // [16]
    float* red  = (float*)(uns2 + 16);   // [80]

    const int tid  = threadIdx.x;
    const int lane = tid & 31;
    const int warp = tid >> 5;
    const int b    = blockIdx.x;
    const float* __restrict__ xb = x + (size_t)b * N0 * CH;

    // ---- colmean + colsum over 49 rows, float4 (threads 0..191) ----
    if (tid < 192) {
        float4 a = make_float4(0.f, 0.f, 0.f, 0.f);
        #pragma unroll 7
        for (int r = 0; r < N0; r++) {
            float4 v = __ldcg((const float4*)(xb + (size_t)r * CH) + tid);
            a.x += v.x; a.y += v.y; a.z += v.z; a.w += v.w;
        }
        ((float4*)csum)[tid] = a;
        float4 m = make_float4(a.x * (1.0f / N0), a.y * (1.0f / N0),
                               a.z * (1.0f / N0), a.w * (1.0f / N0));
        ((float4*)sbuf)[tid] = m;
    }
    __syncthreads();

    // ======================= ROUND 1 (49 -> 36) =============================
    {   // h = gelu(s @ W1 + b1): 6 outputs per warp
        const float4* s4 = (const float4*)sbuf;
        #pragma unroll
        for (int jj = 0; jj < 6; jj++) {
            int j = warp + jj * WARPS;
            float acc = w1_dot(g_w1t[0] + j * CH, s4, lane);
            #pragma unroll
            for (int o = 16; o; o >>= 1) acc += __shfl_xor_sync(0xffffffffu, acc, o);
            if (lane == 0) {
                float z = acc + b1a[j];
                hbuf[j] = 0.5f * z * (1.0f + erff(z * 0.70710678118654752f));
            }
        }
    }
    __syncthreads();

    // gates1: 3 channels per thread (packed W2)
    {
        const uint2* W2p = (const uint2*)g_w2p[0];
        float a0 = b2a[tid]       + w2_dot(W2p, hbuf, tid);
        float a1 = b2a[tid + 256] + w2_dot(W2p, hbuf, tid + 256);
        float a2 = b2a[tid + 512] + w2_dot(W2p, hbuf, tid + 512);
        gat[tid]       = 1.0f / (1.0f + expf(-a0));
        gat[tid + 256] = 1.0f / (1.0f + expf(-a1));
        gat[tid + 512] = 1.0f / (1.0f + expf(-a2));
    }
    __syncthreads();

    // ts1[r] = sum_c (x*g)^2: warp per row, float4
    {
        const float4* g4p = (const float4*)gat;
        #pragma unroll
        for (int ii = 0; ii < 7; ii++) {
            int r = warp + ii * WARPS;
            if (r < N0) {
                const float4* row = (const float4*)(xb + (size_t)r * CH);
                float acc = 0.f;
                #pragma unroll
                for (int k = 0; k < 6; k++) {
                    float4 a = __ldcg(row + lane + 32 * k);
                    float4 g = g4p[lane + 32 * k];
                    float v;
                    v = a.x * g.x; acc += v * v;
                    v = a.y * g.y; acc += v * v;
                    v = a.z * g.z; acc += v * v;
                    v = a.w * g.w; acc += v * v;
                }
                #pragma unroll
                for (int o = 16; o; o >>= 1) acc += __shfl_xor_sync(0xffffffffu, acc, o);
                if (lane == 0) ts[r] = acc;
            }
        }
    }
    __syncthreads();

    // rank-select top-36 (== jax top_k order); 13 unselected to uns
    if (tid < N0) {
        float mine = ts[tid];
        int rank = 0;
        #pragma unroll
        for (int j = 0; j < N0; j++) {
            float tj = ts[j];
            rank += (tj > mine) || (tj == mine && j < tid);
        }
        if (rank < K1) list[rank] = tid;
        else           uns[rank - K1] = tid;
    }
    __syncthreads();

    // ======================= ROUND 2 (36 -> 24) =============================
    // csum36 = csum49 - 13 unselected rows; s2 = gat*csum36/36  (float4)
    if (tid < 192) {
        float4 c = ((float4*)csum)[tid];
        #pragma unroll
        for (int i = 0; i < N0 - K1; i++) {
            float4 v = __ldcg((const float4*)(xb + (size_t)uns[i] * CH) + tid);
            c.x -= v.x; c.y -= v.y; c.z -= v.z; c.w -= v.w;
        }
        ((float4*)csum)[tid] = c;
        float4 g = ((float4*)gat)[tid];
        float4 s = make_float4(c.x * g.x * (1.0f / K1), c.y * g.y * (1.0f / K1),
                               c.z * g.z * (1.0f / K1), c.w * g.w * (1.0f / K1));
        ((float4*)sbuf)[tid] = s;
    }
    __syncthreads();

    {
        const float4* s4 = (const float4*)sbuf;
        #pragma unroll
        for (int jj = 0; jj < 6; jj++) {
            int j = warp + jj * WARPS;
            float acc = w1_dot(g_w1t[1] + j * CH, s4, lane);
            #pragma unroll
            for (int o = 16; o; o >>= 1) acc += __shfl_xor_sync(0xffffffffu, acc, o);
            if (lane == 0) {
                float z = acc + b1b[j];
                hbuf[j] = 0.5f * z * (1.0f + erff(z * 0.70710678118654752f));
            }
        }
    }
    __syncthreads();

    // gat *= gates2
    {
        const uint2* W2p = (const uint2*)g_w2p[1];
        float a0 = b2b[tid]       + w2_dot(W2p, hbuf, tid);
        float a1 = b2b[tid + 256] + w2_dot(W2p, hbuf, tid + 256);
        float a2 = b2b[tid + 512] + w2_dot(W2p, hbuf, tid + 512);
        gat[tid]       *= 1.0f / (1.0f + expf(-a0));
        gat[tid + 256] *= 1.0f / (1.0f + expf(-a1));
        gat[tid + 512] *= 1.0f / (1.0f + expf(-a2));
    }
    __syncthreads();

    // ts2 over 36 selected rows (cumulative gate)
    {
        const float4* g4p = (const float4*)gat;
        #pragma unroll
        for (int ii = 0; ii < 5; ii++) {
            int i = warp + ii * WARPS;
            if (i < K1) {
                const float4* row = (const float4*)(xb + (size_t)list[i] * CH);
                float acc = 0.f;
                #pragma unroll
                for (int k = 0; k < 6; k++) {
                    float4 a = __ldcg(row + lane + 32 * k);
                    float4 g = g4p[lane + 32 * k];
                    float v;
                    v = a.x * g.x; acc += v * v;
                    v = a.y * g.y; acc += v * v;
                    v = a.z * g.z; acc += v * v;
                    v = a.w * g.w; acc += v * v;
                }
                #pragma unroll
                for (int o = 16; o; o >>= 1) acc += __shfl_xor_sync(0xffffffffu, acc, o);
                if (lane == 0) ts[i] = acc;
            }
        }
    }
    __syncthreads();

    // top-24 of 36: record the 12 removed rows
    if (tid < K1) {
        float mine = ts[tid];
        int rank = 0;
        int row = list[tid];
        #pragma unroll
        for (int j = 0; j < K1; j++) {
            float tj = ts[j];
            rank += (tj > mine) || (tj == mine && j < tid);
        }
        if (rank >= K2) uns2[rank - K2] = row;
    }
    __syncthreads();

    // pooled = gat * (csum36 - 12 removed rows) / 24  (float4)
    if (tid < 192) {
        float4 c = ((float4*)csum)[tid];
        #pragma unroll
        for (int i = 0; i < K1 - K2; i++) {
            float4 v = __ldcg((const float4*)(xb + (size_t)uns2[i] * CH) + tid);
            c.x -= v.x; c.y -= v.y; c.z -= v.z; c.w -= v.w;
        }
        float4 g = ((float4*)gat)[tid];
        float4 s = make_float4(c.x * g.x * (1.0f / K2), c.y * g.y * (1.0f / K2),
                               c.z * g.z * (1.0f / K2), c.w * g.w * (1.0f / K2));
        ((float4*)sbuf)[tid] = s;
    }
    __syncthreads();

    // ---- LayerNorm stats ----
    {
        float v0 = sbuf[tid], v1 = sbuf[tid + 256], v2 = sbuf[tid + 512];
        float p1 = v0 + v1 + v2;
        float p2 = v0 * v0 + v1 * v1 + v2 * v2;
        #pragma unroll
        for (int o = 16; o; o >>= 1) {
            p1 += __shfl_xor_sync(0xffffffffu, p1, o);
            p2 += __shfl_xor_sync(0xffffffffu, p2, o);
        }
        if (lane == 0) { red[warp] = p1; red[8 + warp] = p2; }
        __syncthreads();
        if (warp == 0) {
            float m  = (lane < WARPS) ? red[lane]     : 0.f;
            float m2 = (lane < WARPS) ? red[8 + lane] : 0.f;
            #pragma unroll
            for (int o = 4; o; o >>= 1) {
                m  += __shfl_xor_sync(0xffffffffu, m,  o);
                m2 += __shfl_xor_sync(0xffffffffu, m2, o);
            }
            if (lane == 0) {
                m  *= (1.0f / CH);
                m2 *= (1.0f / CH);
                red[16] = m;
                red[17] = rsqrtf(m2 - m * m + 1e-5f);
            }
        }
        __syncthreads();
        float mu = red[16], inv = red[17];
        gat[tid]       = (sbuf[tid]       - mu) * inv * ln_g[tid]       + ln_b[tid];
        gat[tid + 256] = (sbuf[tid + 256] - mu) * inv * ln_g[tid + 256] + ln_b[tid + 256];
        gat[tid + 512] = (sbuf[tid + 512] - mu) * inv * ln_g[tid + 512] + ln_b[tid + 512];
    }
    __syncthreads();

    // ---- classifier: 5 outputs, one warp each ----
    if (warp < 5) {
        const float* wr = g_clswt + warp * CH;
        float acc = 0.f;
        #pragma unroll
        for (int k = 0; k < CH / 32; k++)
            acc += gat[lane + 32 * k] * wr[lane + 32 * k];
        #pragma unroll
        for (int o = 16; o; o >>= 1) acc += __shfl_xor_sync(0xffffffffu, acc, o);
        if (lane == 0) out[b * 5 + warp] = acc + cls_b[warp];
    }
}

extern "C" void kernel_launch(void* const* d_in, const int* in_sizes, int n_in,
                              void* d_out, int out_size) {
    const float* x    = (const float*)d_in[0];
    const float* w1a  = (const float*)d_in[1];
    const float* b1a  = (const float*)d_in[2];
    const float* w2a  = (const float*)d_in[3];
    const float* b2a  = (const float*)d_in[4];
    const float* w1b  = (const float*)d_in[5];
    const float* b1b  = (const float*)d_in[6];
    const float* w2b  = (const float*)d_in[7];
    const float* b2b  = (const float*)d_in[8];
    const float* lng  = (const float*)d_in[9];
    const float* lnb  = (const float*)d_in[10];
    const float* clsw = (const float*)d_in[11];
    const float* clsb = (const float*)d_in[12];
    float* out = (float*)d_out;

    cudaFuncSetAttribute(coatgft_kernel,
                         cudaFuncAttributeMaxDynamicSharedMemorySize, SM_BYTES);

    convert_weights_kernel<<<(MID * CH + 255) / 256, 256>>>(w1a, w2a, w1b, w2b, clsw);
    coatgft_kernel<<<BATCH, THREADS, SM_BYTES>>>(x, b1a, b2a, b1b, b2b,
                                                 lng, lnb, clsb, out);
}